// round 5
// baseline (speedup 1.0000x reference)
#include <cuda_runtime.h>
#include <math.h>

#define NUM_FIELDS 10
#define VOCAB      100000
#define EMBED      8
#define BATCH      16384

#define TPR            16                // threads cooperating on one row
#define ROWS_PER_BLOCK 8
#define THREADS        (TPR * ROWS_PER_BLOCK)   // 128
#define NPAIRS         45
#define PASSES         6                 // 8 pairs per pass (2 lanes/pair), 48 slots >= 45

__global__ __launch_bounds__(THREADS, 16)
void ffm_kernel(const int*   __restrict__ x,
                const float* __restrict__ bias,
                const float* __restrict__ L,
                const float* __restrict__ V,
                float*       __restrict__ out)
{
    __shared__ int sx[ROWS_PER_BLOCK][NUM_FIELDS];
    __shared__ int sI[NPAIRS], sJ[NPAIRS];
    __shared__ int sOij[NPAIRS], sOji[NPAIRS];

    const int tid = threadIdx.x;

    // ---- build pair table (once per block) ----
    if (tid < NPAIRS) {
        int p = tid;
        int i = 0, rem = p;
        while (rem >= (NUM_FIELDS - 1 - i)) { rem -= (NUM_FIELDS - 1 - i); ++i; }
        int j = i + 1 + rem;
        sI[p] = i;
        sJ[p] = j;
        sOij[p] = (i * NUM_FIELDS + j) * VOCAB;
        sOji[p] = (j * NUM_FIELDS + i) * VOCAB;
    }

    // ---- stage x tile for this block's rows ----
    const int row0 = blockIdx.x * ROWS_PER_BLOCK;
    for (int k = tid; k < ROWS_PER_BLOCK * NUM_FIELDS; k += THREADS) {
        ((int*)sx)[k] = x[row0 * NUM_FIELDS + k];
    }
    __syncthreads();

    const int r = tid / TPR;     // local row
    const int t = tid % TPR;     // slot within row group
    const int h = t & 1;         // which 16B half of each vector this lane owns
    const int b = row0 + r;
    const int* xs = sx[r];

    float acc = 0.0f;

    // ---- second order ----
    // Pair p is handled by lane pair (2m, 2m+1): even lane does the lo-half dot,
    // odd lane the hi-half dot. Adjacent lanes address consecutive 16B of the
    // SAME 32B vector -> 2-way coalescing inside every LDG.128 (half the
    // L1tex wavefronts of the previous layout). Halves sum in the final
    // 16-lane reduction for free.
    #pragma unroll
    for (int k = 0; k < PASSES; ++k) {
        const int p = k * (TPR / 2) + (t >> 1);
        if (p < NPAIRS) {
            const int i = sI[p];
            const int j = sJ[p];
            const float4 a = __ldg(reinterpret_cast<const float4*>(
                                 V + (size_t)(sOij[p] + xs[i]) * EMBED) + h);
            const float4 v = __ldg(reinterpret_cast<const float4*>(
                                 V + (size_t)(sOji[p] + xs[j]) * EMBED) + h);
            acc += a.x * v.x + a.y * v.y + a.z * v.z + a.w * v.w;
        }
    }

    // ---- first order: field t (lanes 0..9) ----
    if (t < NUM_FIELDS) {
        acc += __ldg(&L[t * VOCAB + xs[t]]);
    }

    // ---- reduce across the 16-lane row group ----
    acc += __shfl_down_sync(0xffffffffu, acc, 8, 16);
    acc += __shfl_down_sync(0xffffffffu, acc, 4, 16);
    acc += __shfl_down_sync(0xffffffffu, acc, 2, 16);
    acc += __shfl_down_sync(0xffffffffu, acc, 1, 16);

    if (t == 0 && b < BATCH) {
        const float z = acc + __ldg(bias);
        out[b] = 1.0f / (1.0f + expf(-z));
    }
}

extern "C" void kernel_launch(void* const* d_in, const int* in_sizes, int n_in,
                              void* d_out, int out_size)
{
    // Bind inputs by element count (robust to metadata ordering):
    //   x: 16384*10 = 163840 int32
    //   bias: 1 float32
    //   L: 10*100000 = 1,000,000 float32
    //   V: 10*10*100000*8 = 80,000,000 float32
    const int*   x    = nullptr;
    const float* bias = nullptr;
    const float* L    = nullptr;
    const float* V    = nullptr;
    for (int i = 0; i < n_in; ++i) {
        switch (in_sizes[i]) {
            case 163840:   x    = (const int*)  d_in[i]; break;
            case 1:        bias = (const float*)d_in[i]; break;
            case 1000000:  L    = (const float*)d_in[i]; break;
            case 80000000: V    = (const float*)d_in[i]; break;
            default: break;
        }
    }
    float* out = (float*)d_out;

    const int grid = BATCH / ROWS_PER_BLOCK;   // 2048
    ffm_kernel<<<grid, THREADS>>>(x, bias, L, V, out);
}

// round 6
// speedup vs baseline: 1.1896x; 1.1896x over previous
#include <cuda_runtime.h>
#include <math.h>

#define NUM_FIELDS 10
#define VOCAB      100000
#define EMBED      8
#define BATCH      16384

#define TPR            16                // threads cooperating on one row
#define ROWS_PER_BLOCK 8
#define THREADS        (TPR * ROWS_PER_BLOCK)   // 128
#define NPAIRS         45
#define PAIRS_PER_T    3                 // ceil(45/16)

// Ordered slices (i*10+j) with flat index < CACHE_CUT are loaded evict-normal
// (L2-resident across graph replays, ~98MB < 126MB L2); the rest are loaded
// evict-first (streaming) so they never displace the resident set.
#define CACHE_CUT_OFF  (64 * VOCAB)

__global__ __launch_bounds__(THREADS, 16)
void ffm_kernel(const int*   __restrict__ x,
                const float* __restrict__ bias,
                const float* __restrict__ L,
                const float* __restrict__ V,
                float*       __restrict__ out)
{
    __shared__ int sx[ROWS_PER_BLOCK][NUM_FIELDS];
    __shared__ int sI[NPAIRS], sJ[NPAIRS];
    __shared__ int sOij[NPAIRS], sOji[NPAIRS];

    const int tid = threadIdx.x;

    // ---- build pair table (once per block) ----
    if (tid < NPAIRS) {
        int p = tid;
        int i = 0, rem = p;
        while (rem >= (NUM_FIELDS - 1 - i)) { rem -= (NUM_FIELDS - 1 - i); ++i; }
        int j = i + 1 + rem;
        sI[p] = i;
        sJ[p] = j;
        sOij[p] = (i * NUM_FIELDS + j) * VOCAB;
        sOji[p] = (j * NUM_FIELDS + i) * VOCAB;
    }

    // ---- stage x tile for this block's rows ----
    const int row0 = blockIdx.x * ROWS_PER_BLOCK;
    for (int k = tid; k < ROWS_PER_BLOCK * NUM_FIELDS; k += THREADS) {
        ((int*)sx)[k] = x[row0 * NUM_FIELDS + k];
    }
    __syncthreads();

    const int r = tid / TPR;   // local row
    const int t = tid % TPR;   // slot within row group
    const int b = row0 + r;
    const int* xs = sx[r];

    float acc = 0.0f;

    // ---- second order: 45 pairs, strided by TPR, fully unrolled for MLP ----
    #pragma unroll
    for (int k = 0; k < PAIRS_PER_T; ++k) {
        const int p = t + k * TPR;
        if (p < NPAIRS) {
            const int i   = sI[p];
            const int j   = sJ[p];
            const int oA  = sOij[p];
            const int oB  = sOji[p];
            const float4* A  = reinterpret_cast<const float4*>(
                                   V + (size_t)(oA + xs[i]) * EMBED);
            const float4* Bv = reinterpret_cast<const float4*>(
                                   V + (size_t)(oB + xs[j]) * EMBED);
            float4 a0, a1, b0, b1;
            if (oA < CACHE_CUT_OFF) { a0 = __ldg(A);  a1 = __ldg(A + 1); }
            else                    { a0 = __ldcs(A); a1 = __ldcs(A + 1); }
            if (oB < CACHE_CUT_OFF) { b0 = __ldg(Bv);  b1 = __ldg(Bv + 1); }
            else                    { b0 = __ldcs(Bv); b1 = __ldcs(Bv + 1); }
            acc += a0.x * b0.x + a0.y * b0.y + a0.z * b0.z + a0.w * b0.w
                 + a1.x * b1.x + a1.y * b1.y + a1.z * b1.z + a1.w * b1.w;
        }
    }

    // ---- first order: field t (only t < 10 participates) ----
    if (t < NUM_FIELDS) {
        acc += __ldg(&L[t * VOCAB + xs[t]]);
    }

    // ---- reduce across the 16-lane row group ----
    acc += __shfl_down_sync(0xffffffffu, acc, 8, 16);
    acc += __shfl_down_sync(0xffffffffu, acc, 4, 16);
    acc += __shfl_down_sync(0xffffffffu, acc, 2, 16);
    acc += __shfl_down_sync(0xffffffffu, acc, 1, 16);

    if (t == 0 && b < BATCH) {
        const float z = acc + __ldg(bias);
        out[b] = 1.0f / (1.0f + expf(-z));
    }
}

extern "C" void kernel_launch(void* const* d_in, const int* in_sizes, int n_in,
                              void* d_out, int out_size)
{
    // Bind inputs by element count (robust to metadata ordering):
    //   x: 16384*10 = 163840 int32
    //   bias: 1 float32
    //   L: 10*100000 = 1,000,000 float32
    //   V: 10*10*100000*8 = 80,000,000 float32
    const int*   x    = nullptr;
    const float* bias = nullptr;
    const float* L    = nullptr;
    const float* V    = nullptr;
    for (int i = 0; i < n_in; ++i) {
        switch (in_sizes[i]) {
            case 163840:   x    = (const int*)  d_in[i]; break;
            case 1:        bias = (const float*)d_in[i]; break;
            case 1000000:  L    = (const float*)d_in[i]; break;
            case 80000000: V    = (const float*)d_in[i]; break;
            default: break;
        }
    }
    float* out = (float*)d_out;

    const int grid = BATCH / ROWS_PER_BLOCK;   // 2048
    ffm_kernel<<<grid, THREADS>>>(x, bias, L, V, out);
}

// round 7
// speedup vs baseline: 1.2926x; 1.0865x over previous
#include <cuda_runtime.h>
#include <math.h>

#define NUM_FIELDS 10
#define VOCAB      100000
#define EMBED      8
#define BATCH      16384

#define TPR            16                // threads cooperating on one row
#define ROWS_PER_BLOCK 8
#define THREADS        (TPR * ROWS_PER_BLOCK)   // 128
#define NPAIRS         45
#define PAIRS_PER_T    3                 // ceil(45/16)

// Ordered slices (i*10+j) with offset < CACHE_CUT_OFF are loaded evict-normal
// (kept L2-resident across graph replays); the rest are loaded evict-first
// (streaming) so they never displace the resident set.
// 40 slices * 1.54MB ~= 62MB resident, well under the 126MB L2 -> high retention.
#define CACHE_CUT_OFF  (40 * VOCAB)

__global__ __launch_bounds__(THREADS, 16)
void ffm_kernel(const int*   __restrict__ x,
                const float* __restrict__ bias,
                const float* __restrict__ L,
                const float* __restrict__ V,
                float*       __restrict__ out)
{
    __shared__ int sx[ROWS_PER_BLOCK][NUM_FIELDS];
    __shared__ int sI[NPAIRS], sJ[NPAIRS];
    __shared__ int sOij[NPAIRS], sOji[NPAIRS];

    const int tid = threadIdx.x;

    // ---- build pair table (once per block) ----
    if (tid < NPAIRS) {
        int p = tid;
        int i = 0, rem = p;
        while (rem >= (NUM_FIELDS - 1 - i)) { rem -= (NUM_FIELDS - 1 - i); ++i; }
        int j = i + 1 + rem;
        sI[p] = i;
        sJ[p] = j;
        sOij[p] = (i * NUM_FIELDS + j) * VOCAB;
        sOji[p] = (j * NUM_FIELDS + i) * VOCAB;
    }

    // ---- stage x tile for this block's rows ----
    const int row0 = blockIdx.x * ROWS_PER_BLOCK;
    for (int k = tid; k < ROWS_PER_BLOCK * NUM_FIELDS; k += THREADS) {
        ((int*)sx)[k] = x[row0 * NUM_FIELDS + k];
    }
    __syncthreads();

    const int r = tid / TPR;   // local row
    const int t = tid % TPR;   // slot within row group
    const int b = row0 + r;
    const int* xs = sx[r];

    float acc = 0.0f;

    // ---- second order: 45 pairs, strided by TPR, fully unrolled for MLP ----
    #pragma unroll
    for (int k = 0; k < PAIRS_PER_T; ++k) {
        const int p = t + k * TPR;
        if (p < NPAIRS) {
            const int i   = sI[p];
            const int j   = sJ[p];
            const int oA  = sOij[p];
            const int oB  = sOji[p];
            const float4* A  = reinterpret_cast<const float4*>(
                                   V + (size_t)(oA + xs[i]) * EMBED);
            const float4* Bv = reinterpret_cast<const float4*>(
                                   V + (size_t)(oB + xs[j]) * EMBED);
            float4 a0, a1, b0, b1;
            if (oA < CACHE_CUT_OFF) { a0 = __ldg(A);  a1 = __ldg(A + 1); }
            else                    { a0 = __ldcs(A); a1 = __ldcs(A + 1); }
            if (oB < CACHE_CUT_OFF) { b0 = __ldg(Bv);  b1 = __ldg(Bv + 1); }
            else                    { b0 = __ldcs(Bv); b1 = __ldcs(Bv + 1); }
            acc += a0.x * b0.x + a0.y * b0.y + a0.z * b0.z + a0.w * b0.w
                 + a1.x * b1.x + a1.y * b1.y + a1.z * b1.z + a1.w * b1.w;
        }
    }

    // ---- first order: field t (only t < 10 participates) ----
    if (t < NUM_FIELDS) {
        acc += __ldg(&L[t * VOCAB + xs[t]]);
    }

    // ---- reduce across the 16-lane row group ----
    acc += __shfl_down_sync(0xffffffffu, acc, 8, 16);
    acc += __shfl_down_sync(0xffffffffu, acc, 4, 16);
    acc += __shfl_down_sync(0xffffffffu, acc, 2, 16);
    acc += __shfl_down_sync(0xffffffffu, acc, 1, 16);

    if (t == 0 && b < BATCH) {
        const float z = acc + __ldg(bias);
        out[b] = 1.0f / (1.0f + expf(-z));
    }
}

extern "C" void kernel_launch(void* const* d_in, const int* in_sizes, int n_in,
                              void* d_out, int out_size)
{
    // Bind inputs by element count (robust to metadata ordering):
    //   x: 16384*10 = 163840 int32
    //   bias: 1 float32
    //   L: 10*100000 = 1,000,000 float32
    //   V: 10*10*100000*8 = 80,000,000 float32
    const int*   x    = nullptr;
    const float* bias = nullptr;
    const float* L    = nullptr;
    const float* V    = nullptr;
    for (int i = 0; i < n_in; ++i) {
        switch (in_sizes[i]) {
            case 163840:   x    = (const int*)  d_in[i]; break;
            case 1:        bias = (const float*)d_in[i]; break;
            case 1000000:  L    = (const float*)d_in[i]; break;
            case 80000000: V    = (const float*)d_in[i]; break;
            default: break;
        }
    }
    float* out = (float*)d_out;

    const int grid = BATCH / ROWS_PER_BLOCK;   // 2048
    ffm_kernel<<<grid, THREADS>>>(x, bias, L, V, out);
}

// round 9
// speedup vs baseline: 1.4388x; 1.1131x over previous
#include <cuda_runtime.h>
#include <math.h>

#define NUM_FIELDS 10
#define VOCAB      100000
#define EMBED      8
#define BATCH      16384

#define TPR            16                // threads cooperating on one row
#define ROWS_PER_BLOCK 8
#define THREADS        (TPR * ROWS_PER_BLOCK)   // 128
#define NPAIRS         45
#define PAIRS_PER_T    3                 // ceil(45/16)

// Ordered slices (i*10+j) with offset < CACHE_CUT_OFF are pinned in L2 with
// per-instruction L2::evict_last 256-bit loads (sm_103a requires the .v4.b64
// form for this hint). The remaining slices stream with evict-first (__ldcs).
// 48 slices * 1.54MB ~= 74MB pinned < 126MB L2.
#define CACHE_CUT_OFF  (48 * VOCAB)

struct V8 { float f[8]; };

// L2-pinned 32-byte load: one 256-bit ld with lowest L2 eviction priority.
__device__ __forceinline__ V8 ldg_pin32(const float* p) {
    unsigned long long a, b, c, d;
    asm("ld.global.nc.L2::evict_last.v4.b64 {%0,%1,%2,%3}, [%4];"
        : "=l"(a), "=l"(b), "=l"(c), "=l"(d)
        : "l"(p));
    V8 v;
    v.f[0] = __uint_as_float((unsigned)(a));
    v.f[1] = __uint_as_float((unsigned)(a >> 32));
    v.f[2] = __uint_as_float((unsigned)(b));
    v.f[3] = __uint_as_float((unsigned)(b >> 32));
    v.f[4] = __uint_as_float((unsigned)(c));
    v.f[5] = __uint_as_float((unsigned)(c >> 32));
    v.f[6] = __uint_as_float((unsigned)(d));
    v.f[7] = __uint_as_float((unsigned)(d >> 32));
    return v;
}

// Streaming 32-byte load (evict-first) via two 128-bit loads.
__device__ __forceinline__ V8 ldg_stream32(const float* p) {
    const float4 lo = __ldcs(reinterpret_cast<const float4*>(p));
    const float4 hi = __ldcs(reinterpret_cast<const float4*>(p) + 1);
    V8 v;
    v.f[0] = lo.x; v.f[1] = lo.y; v.f[2] = lo.z; v.f[3] = lo.w;
    v.f[4] = hi.x; v.f[5] = hi.y; v.f[6] = hi.z; v.f[7] = hi.w;
    return v;
}

__global__ __launch_bounds__(THREADS, 16)
void ffm_kernel(const int*   __restrict__ x,
                const float* __restrict__ bias,
                const float* __restrict__ L,
                const float* __restrict__ V,
                float*       __restrict__ out)
{
    __shared__ int sx[ROWS_PER_BLOCK][NUM_FIELDS];
    __shared__ int sI[NPAIRS], sJ[NPAIRS];
    __shared__ int sOij[NPAIRS], sOji[NPAIRS];

    const int tid = threadIdx.x;

    // ---- build pair table (once per block) ----
    if (tid < NPAIRS) {
        int p = tid;
        int i = 0, rem = p;
        while (rem >= (NUM_FIELDS - 1 - i)) { rem -= (NUM_FIELDS - 1 - i); ++i; }
        int j = i + 1 + rem;
        sI[p] = i;
        sJ[p] = j;
        sOij[p] = (i * NUM_FIELDS + j) * VOCAB;
        sOji[p] = (j * NUM_FIELDS + i) * VOCAB;
    }

    // ---- stage x tile for this block's rows ----
    const int row0 = blockIdx.x * ROWS_PER_BLOCK;
    for (int k = tid; k < ROWS_PER_BLOCK * NUM_FIELDS; k += THREADS) {
        ((int*)sx)[k] = x[row0 * NUM_FIELDS + k];
    }
    __syncthreads();

    const int r = tid / TPR;   // local row
    const int t = tid % TPR;   // slot within row group
    const int b = row0 + r;
    const int* xs = sx[r];

    float acc = 0.0f;

    // ---- second order: 45 pairs, strided by TPR, fully unrolled for MLP ----
    #pragma unroll
    for (int k = 0; k < PAIRS_PER_T; ++k) {
        const int p = t + k * TPR;
        if (p < NPAIRS) {
            const int i   = sI[p];
            const int j   = sJ[p];
            const int oA  = sOij[p];
            const int oB  = sOji[p];
            const float* A  = V + (size_t)(oA + xs[i]) * EMBED;
            const float* Bv = V + (size_t)(oB + xs[j]) * EMBED;
            const V8 a = (oA < CACHE_CUT_OFF) ? ldg_pin32(A)  : ldg_stream32(A);
            const V8 v = (oB < CACHE_CUT_OFF) ? ldg_pin32(Bv) : ldg_stream32(Bv);
            #pragma unroll
            for (int e = 0; e < 8; ++e) acc += a.f[e] * v.f[e];
        }
    }

    // ---- first order: field t (only t < 10 participates) ----
    if (t < NUM_FIELDS) {
        acc += __ldg(&L[t * VOCAB + xs[t]]);
    }

    // ---- reduce across the 16-lane row group ----
    acc += __shfl_down_sync(0xffffffffu, acc, 8, 16);
    acc += __shfl_down_sync(0xffffffffu, acc, 4, 16);
    acc += __shfl_down_sync(0xffffffffu, acc, 2, 16);
    acc += __shfl_down_sync(0xffffffffu, acc, 1, 16);

    if (t == 0 && b < BATCH) {
        const float z = acc + __ldg(bias);
        out[b] = 1.0f / (1.0f + expf(-z));
    }
}

extern "C" void kernel_launch(void* const* d_in, const int* in_sizes, int n_in,
                              void* d_out, int out_size)
{
    // Bind inputs by element count (robust to metadata ordering):
    //   x: 16384*10 = 163840 int32
    //   bias: 1 float32
    //   L: 10*100000 = 1,000,000 float32
    //   V: 10*10*100000*8 = 80,000,000 float32
    const int*   x    = nullptr;
    const float* bias = nullptr;
    const float* L    = nullptr;
    const float* V    = nullptr;
    for (int i = 0; i < n_in; ++i) {
        switch (in_sizes[i]) {
            case 163840:   x    = (const int*)  d_in[i]; break;
            case 1:        bias = (const float*)d_in[i]; break;
            case 1000000:  L    = (const float*)d_in[i]; break;
            case 80000000: V    = (const float*)d_in[i]; break;
            default: break;
        }
    }
    float* out = (float*)d_out;

    const int grid = BATCH / ROWS_PER_BLOCK;   // 2048
    ffm_kernel<<<grid, THREADS>>>(x, bias, L, V, out);
}